// round 17
// baseline (speedup 1.0000x reference)
#include <cuda_runtime.h>
#include <cstdint>

// IPLayer segment-sum: out[atom][g] += inter[pair][g] for atom = ind_2[pair][0]
// Inputs (metadata order): ind_2 (int32, N_PAIRS*2), prop (float32, N_ATOMS*128),
//                          inter (float32, N_PAIRS*64). Output: float32 N_ATOMS*64.
//
// Converged dense-sector red.v4 scatter, PP=8 straight-line variant:
// 16 lanes per 256B row; each thread owns 8 consecutive pairs for its chunk.
// 4 int4 index loads + 8 float4 row loads front-batched (MLP=12), then 8
// back-to-back red.global.add.v4.f32 -> longer RED bursts, fewer load/RED
// phase boundaries. Traffic identical to champion (~1.66GB LTS-transit).

#define N_INTER 64
#define F4 (N_INTER / 4)   // 16
#define PP 8               // pairs per thread

__global__ void zero_out_kernel(float4* __restrict__ out, int n4) {
    int i = blockIdx.x * blockDim.x + threadIdx.x;
    if (i < n4) out[i] = make_float4(0.f, 0.f, 0.f, 0.f);
}

__global__ void __launch_bounds__(1024) seg_red_kernel(
        const int* __restrict__ ind2,
        const float4* __restrict__ inter,
        float* __restrict__ out,
        int n_pairs) {
    int i = blockIdx.x * blockDim.x + threadIdx.x;
    int g = i >> 4;          // pair-group index (PP pairs)
    int c = i & 15;          // float4 chunk within the 64-float row
    int p0 = g * PP;
    if (p0 >= n_pairs) return;

    if (p0 + PP <= n_pairs) {
        // 4 x 16B index loads cover pairs p0..p7 (32B-aligned: p0 % 8 == 0).
        int4 i01 = __ldcs((const int4*)&ind2[2 * p0 + 0]);   // p0:.x p1:.z
        int4 i23 = __ldcs((const int4*)&ind2[2 * p0 + 4]);   // p2:.x p3:.z
        int4 i45 = __ldcs((const int4*)&ind2[2 * p0 + 8]);   // p4:.x p5:.z
        int4 i67 = __ldcs((const int4*)&ind2[2 * p0 + 12]);  // p6:.x p7:.z
        int a[PP] = { i01.x, i01.z, i23.x, i23.z, i45.x, i45.z, i67.x, i67.z };

        // 8 independent streaming row loads (front-batched -> MLP>=8).
        const float4* src = inter + (size_t)p0 * F4 + c;
        float4 v[PP];
#pragma unroll
        for (int j = 0; j < PP; j++)
            v[j] = __ldcs(src + (size_t)j * F4);

        // 8 back-to-back dense-sector vector reductions.
#pragma unroll
        for (int j = 0; j < PP; j++) {
            float* dst = out + (size_t)a[j] * N_INTER + c * 4;
            asm volatile("red.global.add.v4.f32 [%0], {%1,%2,%3,%4};"
                         :: "l"(dst), "f"(v[j].x), "f"(v[j].y), "f"(v[j].z), "f"(v[j].w)
                         : "memory");
        }
    } else {
        // Tail: per-pair.
        for (int p = p0; p < n_pairs; p++) {
            int a = __ldcs(&ind2[2 * p]);
            float4 v = __ldcs(&inter[(size_t)p * F4 + c]);
            float* dst = out + (size_t)a * N_INTER + c * 4;
            asm volatile("red.global.add.v4.f32 [%0], {%1,%2,%3,%4};"
                         :: "l"(dst), "f"(v.x), "f"(v.y), "f"(v.z), "f"(v.w) : "memory");
        }
    }
}

extern "C" void kernel_launch(void* const* d_in, const int* in_sizes, int n_in,
                              void* d_out, int out_size) {
    const int*    ind2  = (const int*)d_in[0];
    const float4* inter = (const float4*)d_in[2];
    float*        out   = (float*)d_out;

    int n_pairs = in_sizes[0] / 2;

    // Zero the (poisoned) output; plain stores allocate the rows in L2
    // where the subsequent REDs hit.
    int n4 = out_size / 4;
    zero_out_kernel<<<(n4 + 511) / 512, 512>>>((float4*)out, n4);

    // Scatter-add: 16 lanes x PP pairs per thread, block-per-data launch.
    int n_groups = (n_pairs + PP - 1) / PP;
    long long n_work = (long long)n_groups * 16;
    int blocks = (int)((n_work + 1023) / 1024);
    seg_red_kernel<<<blocks, 1024>>>(ind2, inter, out, n_pairs);
}